// round 1
// baseline (speedup 1.0000x reference)
#include <cuda_runtime.h>

#define CD 768
#define ND 4096
#define BB 8

// attn scratch: [B, C, C] fp32 = 18.9 MB
__device__ float g_attn[(size_t)BB * CD * CD];

__device__ __constant__ float kScale = 0.10206207261596577f; // (768/8)^-0.5

// ---------------------------------------------------------------------------
// GEMM1: A[b] = scale * x1[b]^T @ x2[b]
//   x1, x2: [N=4096 rows][C=768 cols] (k-major rows, m/n contiguous)
//   attn[m][n] = scale * sum_k x1[k][m] * x2[k][n]
// 64x64 tile, BK=16, 256 threads, 4x4 per thread.
// ---------------------------------------------------------------------------
__global__ __launch_bounds__(256) void gemm1_kernel(const float* __restrict__ x1,
                                                    const float* __restrict__ x2) {
    __shared__ float As[16][64];
    __shared__ float Bs[16][64];

    const int b  = blockIdx.z;
    const int m0 = blockIdx.y * 64;
    const int n0 = blockIdx.x * 64;

    const float* A = x1 + (size_t)b * ND * CD;
    const float* B = x2 + (size_t)b * ND * CD;

    const int tid = threadIdx.x;
    const int tx  = tid & 15;          // 0..15 (n sub-tile)
    const int ty  = tid >> 4;          // 0..15 (m sub-tile)
    const int lk  = tid >> 4;          // load row in k (0..15)
    const int lm  = (tid & 15) * 4;    // load col (0..60)

    float acc[4][4] = {};

    for (int k0 = 0; k0 < ND; k0 += 16) {
        *(float4*)&As[lk][lm] = *(const float4*)&A[(size_t)(k0 + lk) * CD + m0 + lm];
        *(float4*)&Bs[lk][lm] = *(const float4*)&B[(size_t)(k0 + lk) * CD + n0 + lm];
        __syncthreads();
#pragma unroll
        for (int k = 0; k < 16; k++) {
            float4 av = *(float4*)&As[k][ty * 4];
            float4 bv = *(float4*)&Bs[k][tx * 4];
            float a[4] = {av.x, av.y, av.z, av.w};
            float bb[4] = {bv.x, bv.y, bv.z, bv.w};
#pragma unroll
            for (int i = 0; i < 4; i++)
#pragma unroll
                for (int j = 0; j < 4; j++) acc[i][j] = fmaf(a[i], bb[j], acc[i][j]);
        }
        __syncthreads();
    }

    float* O = g_attn + (size_t)b * CD * CD;
#pragma unroll
    for (int i = 0; i < 4; i++) {
        float4 v = make_float4(acc[i][0] * kScale, acc[i][1] * kScale,
                               acc[i][2] * kScale, acc[i][3] * kScale);
        *(float4*)&O[(size_t)(m0 + ty * 4 + i) * CD + n0 + tx * 4] = v;
    }
}

// ---------------------------------------------------------------------------
// Softmax along last dim of g_attn rows. One block per row (B*C = 6144 rows,
// 768 elems/row, 256 threads, 3 elems/thread).
// ---------------------------------------------------------------------------
__global__ __launch_bounds__(256) void softmax_kernel() {
    float* p = g_attn + (size_t)blockIdx.x * CD;
    const int tid = threadIdx.x;

    float v0 = p[tid];
    float v1 = p[tid + 256];
    float v2 = p[tid + 512];

    float m = fmaxf(fmaxf(v0, v1), v2);
#pragma unroll
    for (int o = 16; o > 0; o >>= 1) m = fmaxf(m, __shfl_xor_sync(0xffffffffu, m, o));

    __shared__ float sm[8];
    __shared__ float ss[8];
    if ((tid & 31) == 0) sm[tid >> 5] = m;
    __syncthreads();

    float bm = sm[0];
#pragma unroll
    for (int i = 1; i < 8; i++) bm = fmaxf(bm, sm[i]);

    float e0 = __expf(v0 - bm);
    float e1 = __expf(v1 - bm);
    float e2 = __expf(v2 - bm);

    float s = e0 + e1 + e2;
#pragma unroll
    for (int o = 16; o > 0; o >>= 1) s += __shfl_xor_sync(0xffffffffu, s, o);
    if ((tid & 31) == 0) ss[tid >> 5] = s;
    __syncthreads();

    float bs = 0.f;
#pragma unroll
    for (int i = 0; i < 8; i++) bs += ss[i];

    float inv = 1.0f / bs;
    p[tid]       = e0 * inv;
    p[tid + 256] = e1 * inv;
    p[tid + 512] = e2 * inv;
}

// ---------------------------------------------------------------------------
// GEMM2: out[b][c][n] = sum_d attn[b][c][d] * x2[b][n][d]
//   attn: [C rows][C cols] row-major (contiguous in d=k)
//   x2:   [N rows][C cols] row-major (contiguous in d=k)
// Both operands transposed into smem (pad 65 to kill store conflicts).
// ---------------------------------------------------------------------------
__global__ __launch_bounds__(256) void gemm2_kernel(const float* __restrict__ x2,
                                                    float* __restrict__ out) {
    __shared__ float As[16][65];
    __shared__ float Bs[16][65];

    const int b  = blockIdx.z;
    const int m0 = blockIdx.y * 64;  // c tile
    const int n0 = blockIdx.x * 64;  // n tile

    const float* A = g_attn + (size_t)b * CD * CD;
    const float* B = x2 + (size_t)b * ND * CD;

    const int tid = threadIdx.x;
    const int tx  = tid & 15;
    const int ty  = tid >> 4;
    const int lr  = tid >> 2;        // row 0..63 within tile
    const int lk  = (tid & 3) * 4;   // k offset 0,4,8,12

    float acc[4][4] = {};

    for (int k0 = 0; k0 < CD; k0 += 16) {
        float4 va = *(const float4*)&A[(size_t)(m0 + lr) * CD + k0 + lk];
        float4 vb = *(const float4*)&B[(size_t)(n0 + lr) * CD + k0 + lk];
        As[lk + 0][lr] = va.x; As[lk + 1][lr] = va.y;
        As[lk + 2][lr] = va.z; As[lk + 3][lr] = va.w;
        Bs[lk + 0][lr] = vb.x; Bs[lk + 1][lr] = vb.y;
        Bs[lk + 2][lr] = vb.z; Bs[lk + 3][lr] = vb.w;
        __syncthreads();
#pragma unroll
        for (int k = 0; k < 16; k++) {
            float a[4], bb[4];
#pragma unroll
            for (int i = 0; i < 4; i++) a[i] = As[k][ty * 4 + i];
#pragma unroll
            for (int j = 0; j < 4; j++) bb[j] = Bs[k][tx * 4 + j];
#pragma unroll
            for (int i = 0; i < 4; i++)
#pragma unroll
                for (int j = 0; j < 4; j++) acc[i][j] = fmaf(a[i], bb[j], acc[i][j]);
        }
        __syncthreads();
    }

    float* O = out + (size_t)b * CD * ND;
#pragma unroll
    for (int i = 0; i < 4; i++) {
        float4 v = make_float4(acc[i][0], acc[i][1], acc[i][2], acc[i][3]);
        *(float4*)&O[(size_t)(m0 + ty * 4 + i) * ND + n0 + tx * 4] = v;
    }
}

extern "C" void kernel_launch(void* const* d_in, const int* in_sizes, int n_in,
                              void* d_out, int out_size) {
    const float* x1 = (const float*)d_in[0];
    const float* x2 = (const float*)d_in[1];
    float* out = (float*)d_out;

    dim3 g1(CD / 64, CD / 64, BB);     // 12 x 12 x 8
    gemm1_kernel<<<g1, 256>>>(x1, x2);

    softmax_kernel<<<BB * CD, 256>>>();

    dim3 g2(ND / 64, CD / 64, BB);     // 64 x 12 x 8
    gemm2_kernel<<<g2, 256>>>(x2, out);
}

// round 3
// speedup vs baseline: 2.9863x; 2.9863x over previous
#include <cuda_runtime.h>
#include <cuda_bf16.h>
#include <cstdint>

#define CD 768
#define ND 4096
#define BB 8

using bf16 = __nv_bfloat16;

// ---------------------------------------------------------------------------
// Device scratch (module-load allocated; no runtime allocs)
// ---------------------------------------------------------------------------
__device__ bf16 g_x1t_hi[(size_t)BB * CD * ND];  // x1^T [b][c][n], bf16 hi
__device__ bf16 g_x1t_lo[(size_t)BB * CD * ND];
__device__ bf16 g_x2t_hi[(size_t)BB * CD * ND];  // x2^T [b][c][n]
__device__ bf16 g_x2t_lo[(size_t)BB * CD * ND];
__device__ bf16 g_x2n_hi[(size_t)BB * ND * CD];  // x2 natural [b][n][c]
__device__ bf16 g_x2n_lo[(size_t)BB * ND * CD];
__device__ float g_attn[(size_t)BB * CD * CD];   // fp32 logits
__device__ bf16 g_at_hi[(size_t)BB * CD * CD];   // softmaxed attn, bf16 split
__device__ bf16 g_at_lo[(size_t)BB * CD * CD];

__device__ __constant__ float kScale = 0.10206207261596577f;  // (768/8)^-0.5

// ---------------------------------------------------------------------------
// PTX helpers
// ---------------------------------------------------------------------------
__device__ __forceinline__ uint32_t smem_u32(const void* p) {
    uint32_t a;
    asm("{ .reg .u64 t; cvta.to.shared.u64 t, %1; cvt.u32.u64 %0, t; }" : "=r"(a) : "l"(p));
    return a;
}

__device__ __forceinline__ void cp_async16(uint32_t saddr, const void* gaddr) {
    asm volatile("cp.async.cg.shared.global [%0], [%1], 16;" :: "r"(saddr), "l"(gaddr));
}
#define CP_COMMIT() asm volatile("cp.async.commit_group;" ::: "memory")
#define CP_WAIT(n)  asm volatile("cp.async.wait_group %0;" :: "n"(n) : "memory")

__device__ __forceinline__ void ldsm4(uint32_t& r0, uint32_t& r1, uint32_t& r2,
                                      uint32_t& r3, uint32_t addr) {
    asm volatile("ldmatrix.sync.aligned.m8n8.x4.shared.b16 {%0,%1,%2,%3}, [%4];"
                 : "=r"(r0), "=r"(r1), "=r"(r2), "=r"(r3) : "r"(addr));
}

__device__ __forceinline__ void mma_bf16(float* c, const uint32_t* a, const uint32_t* b) {
    asm volatile(
        "mma.sync.aligned.m16n8k16.row.col.f32.bf16.bf16.f32 "
        "{%0,%1,%2,%3}, {%4,%5,%6,%7}, {%8,%9}, {%0,%1,%2,%3};"
        : "+f"(c[0]), "+f"(c[1]), "+f"(c[2]), "+f"(c[3])
        : "r"(a[0]), "r"(a[1]), "r"(a[2]), "r"(a[3]), "r"(b[0]), "r"(b[1]));
}

// ---------------------------------------------------------------------------
// Transpose + bf16 split: src fp32 [b][N][C] -> dstT hi/lo bf16 [b][C][N]
// ---------------------------------------------------------------------------
__global__ __launch_bounds__(256) void tsplit_kernel(const float* __restrict__ src,
                                                     bf16* __restrict__ dh,
                                                     bf16* __restrict__ dl) {
    __shared__ float t[32][33];
    const int b = blockIdx.z;
    const int c0 = blockIdx.x * 32;
    const int n0 = blockIdx.y * 32;
    const int tx = threadIdx.x, ty = threadIdx.y;  // 32 x 8

    const float* s = src + (size_t)b * ND * CD;
#pragma unroll
    for (int i = 0; i < 4; i++)
        t[ty + 8 * i][tx] = s[(size_t)(n0 + ty + 8 * i) * CD + c0 + tx];
    __syncthreads();

    bf16* oh = dh + (size_t)b * CD * ND;
    bf16* ol = dl + (size_t)b * CD * ND;
#pragma unroll
    for (int i = 0; i < 4; i++) {
        float v = t[tx][ty + 8 * i];
        bf16 h = __float2bfloat16(v);
        size_t o = (size_t)(c0 + ty + 8 * i) * ND + n0 + tx;
        oh[o] = h;
        ol[o] = __float2bfloat16(v - __bfloat162float(h));
    }
}

// ---------------------------------------------------------------------------
// Natural-layout bf16 split (x2 used as GEMM2 B operand)
// ---------------------------------------------------------------------------
__global__ __launch_bounds__(256) void nsplit_kernel(const float* __restrict__ src,
                                                     bf16* __restrict__ dh,
                                                     bf16* __restrict__ dl) {
    size_t i = ((size_t)blockIdx.x * 256 + threadIdx.x) * 4;
    float4 v = *(const float4*)(src + i);
    bf16 h0 = __float2bfloat16(v.x), h1 = __float2bfloat16(v.y);
    bf16 h2 = __float2bfloat16(v.z), h3 = __float2bfloat16(v.w);
    __nv_bfloat162 hA = {h0, h1}, hB = {h2, h3};
    __nv_bfloat162 lA = {__float2bfloat16(v.x - __bfloat162float(h0)),
                         __float2bfloat16(v.y - __bfloat162float(h1))};
    __nv_bfloat162 lB = {__float2bfloat16(v.z - __bfloat162float(h2)),
                         __float2bfloat16(v.w - __bfloat162float(h3))};
    *(__nv_bfloat162*)(dh + i) = hA;
    *(__nv_bfloat162*)(dh + i + 2) = hB;
    *(__nv_bfloat162*)(dl + i) = lA;
    *(__nv_bfloat162*)(dl + i + 2) = lB;
}

// ---------------------------------------------------------------------------
// Softmax over g_attn rows + bf16 split of the result
// ---------------------------------------------------------------------------
__global__ __launch_bounds__(256) void softmax_kernel() {
    const size_t ro = (size_t)blockIdx.x * CD;
    float* p = g_attn + ro;
    const int tid = threadIdx.x;

    float v0 = p[tid], v1 = p[tid + 256], v2 = p[tid + 512];

    float m = fmaxf(fmaxf(v0, v1), v2);
#pragma unroll
    for (int o = 16; o > 0; o >>= 1) m = fmaxf(m, __shfl_xor_sync(0xffffffffu, m, o));

    __shared__ float sm[8], ss[8];
    if ((tid & 31) == 0) sm[tid >> 5] = m;
    __syncthreads();
    float bm = sm[0];
#pragma unroll
    for (int i = 1; i < 8; i++) bm = fmaxf(bm, sm[i]);

    float e0 = __expf(v0 - bm), e1 = __expf(v1 - bm), e2 = __expf(v2 - bm);
    float s = e0 + e1 + e2;
#pragma unroll
    for (int o = 16; o > 0; o >>= 1) s += __shfl_xor_sync(0xffffffffu, s, o);
    if ((tid & 31) == 0) ss[tid >> 5] = s;
    __syncthreads();
    float bs = 0.f;
#pragma unroll
    for (int i = 0; i < 8; i++) bs += ss[i];

    float inv = 1.0f / bs;
#pragma unroll
    for (int j = 0; j < 3; j++) {
        float v = (j == 0 ? e0 : j == 1 ? e1 : e2) * inv;
        bf16 h = __float2bfloat16(v);
        size_t o = ro + tid + j * 256;
        g_at_hi[o] = h;
        g_at_lo[o] = __float2bfloat16(v - __bfloat162float(h));
    }
}

// ---------------------------------------------------------------------------
// HMMA bf16x3 GEMM: D[m][n] = sum_k A[m][k]*B[n][k], K-contiguous operands.
// CTA tile 128x128, BK=32, 8 warps (warp tile 64x32), cp.async double buffer.
// Smem rows padded to 80B (stride-20-word: conflict-free ldmatrix).
// ---------------------------------------------------------------------------
static constexpr int ROWB = 80;                 // bytes per smem row (32 bf16 + 8 pad)
static constexpr int TEN = 128 * ROWB;          // 10240B per tensor tile
static constexpr int STG = 4 * TEN;             // Ah,Al,Bh,Bl = 40960B per stage
static constexpr int SM_TOTAL = 2 * STG;        // 81920

template <int K, int NTOT, bool PH1>
__global__ __launch_bounds__(256) void hgemm_kernel(float* __restrict__ Cout) {
    extern __shared__ char smc[];
    const uint32_t smb = smem_u32(smc);
    const int tid = threadIdx.x;
    const int wid = tid >> 5, lane = tid & 31;
    const int wm = wid >> 2, wn = wid & 3;
    const int b = blockIdx.z;
    const int m0 = blockIdx.y * 128;
    const int n0 = blockIdx.x * 128;

    const bf16 *pAh, *pAl, *pBh, *pBl;
    float* Cp;
    if constexpr (PH1) {
        pAh = g_x1t_hi + (size_t)b * CD * ND + (size_t)m0 * ND;
        pAl = g_x1t_lo + (size_t)b * CD * ND + (size_t)m0 * ND;
        pBh = g_x2t_hi + (size_t)b * CD * ND + (size_t)n0 * ND;
        pBl = g_x2t_lo + (size_t)b * CD * ND + (size_t)n0 * ND;
        Cp = g_attn + (size_t)b * CD * CD;
    } else {
        pAh = g_at_hi + (size_t)b * CD * CD + (size_t)m0 * CD;
        pAl = g_at_lo + (size_t)b * CD * CD + (size_t)m0 * CD;
        pBh = g_x2n_hi + (size_t)b * ND * CD + (size_t)n0 * CD;
        pBl = g_x2n_lo + (size_t)b * ND * CD + (size_t)n0 * CD;
        Cp = Cout + (size_t)b * CD * ND;
    }

    const int lrow = tid >> 2;          // 0..63 (row pair base: handles row, row+64? no: see below)
    const int lseg = tid & 3;           // 16B segment within 64B row payload

    // issue one stage: 128 rows per tensor; thread handles rows lrow and lrow+64
    auto issue = [&](int c, int buf) {
        const int k0 = c * 32;
        const uint32_t sb = smb + buf * STG;
#pragma unroll
        for (int h = 0; h < 2; h++) {
            const int row = lrow + h * 64;
            const uint32_t so = (uint32_t)row * ROWB + lseg * 16;
            const size_t go = (size_t)row * K + k0 + lseg * 8;
            cp_async16(sb + so, pAh + go);
            cp_async16(sb + TEN + so, pAl + go);
            cp_async16(sb + 2 * TEN + so, pBh + go);
            cp_async16(sb + 3 * TEN + so, pBl + go);
        }
        CP_COMMIT();
    };

    float acc[4][4][4] = {};
    constexpr int NC = K / 32;

    issue(0, 0);

    for (int c = 0; c < NC; c++) {
        const int buf = c & 1;
        if (c + 1 < NC) {
            issue(c + 1, buf ^ 1);
            CP_WAIT(1);
        } else {
            CP_WAIT(0);
        }
        __syncthreads();

        const uint32_t sA = smb + buf * STG;
        const uint32_t sB = sA + 2 * TEN;

        // A lane addressing: row_in = lane%16, k-half = lane>>4
        const int a_r = lane & 15, a_h = lane >> 4;
        // B lane addressing: tile = lane>>3; row_in = (lane&7)+ (tile>>1)*8; k-half = tile&1
        const int b_r = (lane & 7) + ((lane >> 4) << 3);  // (tile>>1)*8 == (lane>>4)*8
        const int b_h = (lane >> 3) & 1;

#pragma unroll
        for (int ks = 0; ks < 2; ks++) {
            const uint32_t kso = ks * 32;  // 16 bf16 = 32B
            uint32_t ah[4][4], al[4][4], bh[2][4], bl[2][4];
#pragma unroll
            for (int mt = 0; mt < 4; mt++) {
                uint32_t addr = sA + (uint32_t)(wm * 64 + mt * 16 + a_r) * ROWB + kso + a_h * 16;
                ldsm4(ah[mt][0], ah[mt][1], ah[mt][2], ah[mt][3], addr);
                ldsm4(al[mt][0], al[mt][1], al[mt][2], al[mt][3], addr + TEN);
            }
#pragma unroll
            for (int np = 0; np < 2; np++) {
                uint32_t addr = sB + (uint32_t)(wn * 32 + np * 16 + b_r) * ROWB + kso + b_h * 16;
                ldsm4(bh[np][0], bh[np][1], bh[np][2], bh[np][3], addr);
                ldsm4(bl[np][0], bl[np][1], bl[np][2], bl[np][3], addr + TEN);
            }
#pragma unroll
            for (int mt = 0; mt < 4; mt++)
#pragma unroll
                for (int nt = 0; nt < 4; nt++) {
                    const uint32_t* bph = &bh[nt >> 1][(nt & 1) * 2];
                    const uint32_t* bpl = &bl[nt >> 1][(nt & 1) * 2];
                    mma_bf16(acc[mt][nt], ah[mt], bph);
                    mma_bf16(acc[mt][nt], ah[mt], bpl);
                    mma_bf16(acc[mt][nt], al[mt], bph);
                }
        }
        __syncthreads();
    }

    // epilogue
    const int er = lane >> 2, ec = (lane & 3) * 2;
#pragma unroll
    for (int mt = 0; mt < 4; mt++) {
#pragma unroll
        for (int nt = 0; nt < 4; nt++) {
            float* a4 = acc[mt][nt];
            if constexpr (PH1) {
#pragma unroll
                for (int i = 0; i < 4; i++) a4[i] *= kScale;
            }
            const int row = m0 + wm * 64 + mt * 16 + er;
            const int col = n0 + wn * 32 + nt * 8 + ec;
            *(float2*)(Cp + (size_t)row * NTOT + col) = make_float2(a4[0], a4[1]);
            *(float2*)(Cp + (size_t)(row + 8) * NTOT + col) = make_float2(a4[2], a4[3]);
        }
    }
}

// ---------------------------------------------------------------------------
extern "C" void kernel_launch(void* const* d_in, const int* in_sizes, int n_in,
                              void* d_out, int out_size) {
    const float* x1 = (const float*)d_in[0];
    const float* x2 = (const float*)d_in[1];
    float* out = (float*)d_out;

    cudaFuncSetAttribute(hgemm_kernel<ND, CD, true>,
                         cudaFuncAttributeMaxDynamicSharedMemorySize, SM_TOTAL);
    cudaFuncSetAttribute(hgemm_kernel<CD, ND, false>,
                         cudaFuncAttributeMaxDynamicSharedMemorySize, SM_TOTAL);

    bf16 *x1t_hi, *x1t_lo, *x2t_hi, *x2t_lo, *x2n_hi, *x2n_lo;
    cudaGetSymbolAddress((void**)&x1t_hi, g_x1t_hi);
    cudaGetSymbolAddress((void**)&x1t_lo, g_x1t_lo);
    cudaGetSymbolAddress((void**)&x2t_hi, g_x2t_hi);
    cudaGetSymbolAddress((void**)&x2t_lo, g_x2t_lo);
    cudaGetSymbolAddress((void**)&x2n_hi, g_x2n_hi);
    cudaGetSymbolAddress((void**)&x2n_lo, g_x2n_lo);

    dim3 tb(32, 8);
    dim3 tg(CD / 32, ND / 32, BB);
    tsplit_kernel<<<tg, tb>>>(x1, x1t_hi, x1t_lo);
    tsplit_kernel<<<tg, tb>>>(x2, x2t_hi, x2t_lo);
    nsplit_kernel<<<(size_t)BB * ND * CD / 1024, 256>>>(x2, x2n_hi, x2n_lo);

    dim3 g1(CD / 128, CD / 128, BB);  // 6 x 6 x 8
    hgemm_kernel<ND, CD, true><<<g1, 256, SM_TOTAL>>>(nullptr);

    softmax_kernel<<<BB * CD, 256>>>();

    dim3 g2(ND / 128, CD / 128, BB);  // 32 x 6 x 8
    hgemm_kernel<CD, ND, false><<<g2, 256, SM_TOTAL>>>(out);
}